// round 2
// baseline (speedup 1.0000x reference)
#include <cuda_runtime.h>

// ---------------- constants ----------------
#define B_   16
#define N_   4096
#define M_   77
#define QDIM 1024
#define CDIM 768
#define H_   8
#define D_   64
#define INNER (H_*D_)   // 512

// ---------------- scratch (device globals: allocation-free) ----------------
__device__ float g_q[(long)B_*N_*INNER];     // 134 MB
__device__ float g_k[(long)B_*M_*INNER];     // 2.5 MB
__device__ float g_v[(long)B_*M_*INNER];     // 2.5 MB
__device__ float g_a[(long)B_*N_*INNER];     // 134 MB

// ---------------- generic guarded SGEMM: C = A(MxK) @ B(KxN) [+bias] ----------------
// Tile: BM=128, BN=128, BK=16; 256 threads, 8x8 per thread.
// Requires: N % 128 == 0, K % 16 == 0 (true for all call sites). M may be ragged.
#define BM 128
#define BN 128
#define BK 16
#define TM 8
#define TN 8

__global__ __launch_bounds__(256) void sgemm_bias(
    int M, int N, int K,
    const float* __restrict__ A, const float* __restrict__ Bm,
    const float* __restrict__ bias, float* __restrict__ C)
{
    __shared__ float As[BK][BM];
    __shared__ float Bs[BK][BN];

    const int tid = threadIdx.x;
    const int rowBase = blockIdx.y * BM;
    const int colBase = blockIdx.x * BN;

    // A loader: 64 rows per step, 4 float4-columns (BK=16)
    const int aRow = tid >> 2;          // 0..63
    const int aCol = (tid & 3) << 2;    // 0,4,8,12
    // B loader: 8 k-rows per step, 32 float4-columns (BN=128)
    const int bRow = tid >> 5;          // 0..7
    const int bCol = (tid & 31) << 2;   // 0..124

    const int tRow = (tid >> 4) * TM;   // 0..120
    const int tCol = (tid & 15) * TN;   // 0..120

    float acc[TM][TN];
    #pragma unroll
    for (int i = 0; i < TM; i++)
        #pragma unroll
        for (int j = 0; j < TN; j++) acc[i][j] = 0.f;

    for (int k0 = 0; k0 < K; k0 += BK) {
        #pragma unroll
        for (int r = 0; r < BM; r += 64) {
            int gr = rowBase + aRow + r;
            float4 t = make_float4(0.f, 0.f, 0.f, 0.f);
            if (gr < M)
                t = *reinterpret_cast<const float4*>(&A[(long)gr * K + k0 + aCol]);
            As[aCol + 0][aRow + r] = t.x;
            As[aCol + 1][aRow + r] = t.y;
            As[aCol + 2][aRow + r] = t.z;
            As[aCol + 3][aRow + r] = t.w;
        }
        #pragma unroll
        for (int r = 0; r < BK; r += 8) {
            int gk = k0 + bRow + r;
            *reinterpret_cast<float4*>(&Bs[bRow + r][bCol]) =
                *reinterpret_cast<const float4*>(&Bm[(long)gk * N + colBase + bCol]);
        }
        __syncthreads();

        #pragma unroll
        for (int k = 0; k < BK; k++) {
            float regM[TM], regN[TN];
            *reinterpret_cast<float4*>(&regM[0]) = *reinterpret_cast<float4*>(&As[k][tRow]);
            *reinterpret_cast<float4*>(&regM[4]) = *reinterpret_cast<float4*>(&As[k][tRow + 4]);
            *reinterpret_cast<float4*>(&regN[0]) = *reinterpret_cast<float4*>(&Bs[k][tCol]);
            *reinterpret_cast<float4*>(&regN[4]) = *reinterpret_cast<float4*>(&Bs[k][tCol + 4]);
            #pragma unroll
            for (int i = 0; i < TM; i++)
                #pragma unroll
                for (int j = 0; j < TN; j++)
                    acc[i][j] += regM[i] * regN[j];
        }
        __syncthreads();
    }

    #pragma unroll
    for (int i = 0; i < TM; i++) {
        int gr = rowBase + tRow + i;
        if (gr < M) {
            #pragma unroll
            for (int j = 0; j < TN; j += 4) {
                int gc = colBase + tCol + j;
                float4 o;
                o.x = acc[i][j + 0]; o.y = acc[i][j + 1];
                o.z = acc[i][j + 2]; o.w = acc[i][j + 3];
                if (bias) {
                    o.x += bias[gc + 0]; o.y += bias[gc + 1];
                    o.z += bias[gc + 2]; o.w += bias[gc + 3];
                }
                *reinterpret_cast<float4*>(&C[(long)gr * N + gc]) = o;
            }
        }
    }
}

// ---------------- fused flash-style attention ----------------
// grid = (N/128, H, B), 128 threads; one query row per thread.
// K/V tiles (77x64 each) staged in smem; online softmax with branchy rescale.
__global__ __launch_bounds__(128) void attn_kernel(
    const float* __restrict__ q, const float* __restrict__ kbuf,
    const float* __restrict__ vbuf, float* __restrict__ out)
{
    __shared__ float Ks[M_][D_];
    __shared__ float Vs[M_][D_];

    const int b = blockIdx.z, h = blockIdx.y;
    const int tid = threadIdx.x;
    const int n = blockIdx.x * 128 + tid;
    const float scale = 0.125f;  // 1/sqrt(64)

    const long kvbase = ((long)b * M_) * INNER + h * D_;
    for (int idx = tid; idx < M_ * (D_ / 4); idx += 128) {
        int m = idx >> 4;
        int d4 = (idx & 15) << 2;
        *reinterpret_cast<float4*>(&Ks[m][d4]) =
            *reinterpret_cast<const float4*>(&kbuf[kvbase + (long)m * INNER + d4]);
        *reinterpret_cast<float4*>(&Vs[m][d4]) =
            *reinterpret_cast<const float4*>(&vbuf[kvbase + (long)m * INNER + d4]);
    }
    __syncthreads();

    float qr[D_];
    const long qbase = ((long)b * N_ + n) * INNER + h * D_;
    #pragma unroll
    for (int d4 = 0; d4 < D_; d4 += 4) {
        float4 t = *reinterpret_cast<const float4*>(&q[qbase + d4]);
        qr[d4 + 0] = t.x * scale; qr[d4 + 1] = t.y * scale;
        qr[d4 + 2] = t.z * scale; qr[d4 + 3] = t.w * scale;
    }

    float acc[D_];
    #pragma unroll
    for (int d = 0; d < D_; d++) acc[d] = 0.f;
    float mrun = -1e30f, srun = 0.f;

    for (int m = 0; m < M_; m++) {
        float s = 0.f;
        #pragma unroll
        for (int d = 0; d < D_; d++) s += qr[d] * Ks[m][d];
        if (s <= mrun) {
            float p = __expf(s - mrun);
            srun += p;
            #pragma unroll
            for (int d = 0; d < D_; d++) acc[d] += p * Vs[m][d];
        } else {
            float corr = __expf(mrun - s);
            mrun = s;
            srun = srun * corr + 1.f;
            #pragma unroll
            for (int d = 0; d < D_; d++) acc[d] = acc[d] * corr + Vs[m][d];
        }
    }

    const float inv = 1.f / srun;
    #pragma unroll
    for (int d4 = 0; d4 < D_; d4 += 4) {
        float4 o;
        o.x = acc[d4 + 0] * inv; o.y = acc[d4 + 1] * inv;
        o.z = acc[d4 + 2] * inv; o.w = acc[d4 + 3] * inv;
        *reinterpret_cast<float4*>(&out[qbase + d4]) = o;
    }
}

// ---------------- launch ----------------
extern "C" void kernel_launch(void* const* d_in, const int* in_sizes, int n_in,
                              void* d_out, int out_size)
{
    const float* x   = (const float*)d_in[0];
    const float* ctx = (const float*)d_in[1];
    const float* Wq  = (const float*)d_in[2];
    const float* Wk  = (const float*)d_in[3];
    const float* Wv  = (const float*)d_in[4];
    const float* Wo  = (const float*)d_in[5];
    const float* bo  = (const float*)d_in[6];
    float* out = (float*)d_out;

    float *qb, *kb, *vb, *ab;
    cudaGetSymbolAddress((void**)&qb, g_q);
    cudaGetSymbolAddress((void**)&kb, g_k);
    cudaGetSymbolAddress((void**)&vb, g_v);
    cudaGetSymbolAddress((void**)&ab, g_a);

    const int BM_rows_kv = (B_ * M_ + BM - 1) / BM;  // 10

    // k = ctx @ Wk, v = ctx @ Wv   (1232 x 512, K=768)
    sgemm_bias<<<dim3(INNER / BN, BM_rows_kv), 256>>>(B_ * M_, INNER, CDIM, ctx, Wk, nullptr, kb);
    sgemm_bias<<<dim3(INNER / BN, BM_rows_kv), 256>>>(B_ * M_, INNER, CDIM, ctx, Wv, nullptr, vb);

    // q = x @ Wq   (65536 x 512, K=1024)
    sgemm_bias<<<dim3(INNER / BN, (B_ * N_) / BM), 256>>>(B_ * N_, INNER, QDIM, x, Wq, nullptr, qb);

    // attention
    attn_kernel<<<dim3(N_ / 128, H_, B_), 128>>>(qb, kb, vb, ab);

    // out = attn @ Wo + bo   (65536 x 1024, K=512)
    sgemm_bias<<<dim3(QDIM / BN, (B_ * N_) / BM), 256>>>(B_ * N_, QDIM, INNER, ab, Wo, bo, out);
}

// round 4
// speedup vs baseline: 2.1520x; 2.1520x over previous
#include <cuda_runtime.h>
#include <cstdint>

// ---------------- constants ----------------
#define B_   16
#define N_   4096
#define M_   77
#define QDIM 1024
#define CDIM 768
#define H_   8
#define D_   64
#define INNER (H_*D_)   // 512

// ---------------- scratch (device globals: allocation-free) ----------------
__device__ float g_xr[(long)B_*N_*QDIM];    // tf32-rounded x   (268 MB)
__device__ float g_cr[(long)B_*M_*CDIM];    // tf32-rounded ctx
__device__ float g_wq[QDIM*INNER];
__device__ float g_wk[CDIM*INNER];
__device__ float g_wv[CDIM*INNER];
__device__ float g_wo[INNER*QDIM];
__device__ float g_q[(long)B_*N_*INNER];    // 134 MB
__device__ float g_k[(long)B_*M_*INNER];
__device__ float g_v[(long)B_*M_*INNER];
__device__ float g_a[(long)B_*N_*INNER];    // 134 MB (tf32-rounded by attn)

// ---------------- helpers ----------------
__device__ __forceinline__ float tf32r(float x) {
    uint32_t u;
    asm("cvt.rna.tf32.f32 %0, %1;" : "=r"(u) : "f"(x));
    return __uint_as_float(u);
}

__device__ __forceinline__ void cp16(void* smem_dst, const void* gmem_src, bool pred) {
    uint32_t s = (uint32_t)__cvta_generic_to_shared(smem_dst);
    int sz = pred ? 16 : 0;
    asm volatile("cp.async.cg.shared.global [%0], [%1], 16, %2;\n"
                 :: "r"(s), "l"(gmem_src), "r"(sz));
}
__device__ __forceinline__ void cp_commit() {
    asm volatile("cp.async.commit_group;\n" ::: "memory");
}
__device__ __forceinline__ void cp_wait0() {
    asm volatile("cp.async.wait_group 0;\n" ::: "memory");
}

__device__ __forceinline__ void mma_tf32(float c[4], const uint32_t a[4], const uint32_t b[2]) {
    asm volatile(
        "mma.sync.aligned.m16n8k8.row.col.f32.tf32.tf32.f32 "
        "{%0,%1,%2,%3}, {%4,%5,%6,%7}, {%8,%9}, {%0,%1,%2,%3};\n"
        : "+f"(c[0]), "+f"(c[1]), "+f"(c[2]), "+f"(c[3])
        : "r"(a[0]), "r"(a[1]), "r"(a[2]), "r"(a[3]), "r"(b[0]), "r"(b[1]));
}

// ---------------- tf32 rounding pass (vectorized) ----------------
__global__ __launch_bounds__(256) void tf32_round(const float4* __restrict__ in,
                                                  float4* __restrict__ out, int n4) {
    int i = blockIdx.x * 256 + threadIdx.x;
    if (i < n4) {
        float4 v = in[i];
        v.x = tf32r(v.x); v.y = tf32r(v.y); v.z = tf32r(v.z); v.w = tf32r(v.w);
        out[i] = v;
    }
}

// ---------------- tf32 tensor-core GEMM: C = A(MxK) @ B(KxN) [+bias] ----------------
// BM=128, BN=128, BK=16; 256 threads = 8 warps (4 along M x 2 along N), warp tile 32x64.
// A,B pre-rounded to tf32. Requires N%128==0, K%16==0; M may be ragged (guarded).
#define GBM 128
#define GBN 128
#define GBK 16
#define APAD 4   // As row stride 20 floats -> conflict-free frag loads
#define BPAD 8   // Bs row stride 136 floats -> conflict-free frag loads

__global__ __launch_bounds__(256) void sgemm_tf32(
    int M, int N, int K,
    const float* __restrict__ A, const float* __restrict__ Bm,
    const float* __restrict__ bias, float* __restrict__ C)
{
    __shared__ float As[2][GBM][GBK + APAD];
    __shared__ float Bs[2][GBK][GBN + BPAD];

    const int tid  = threadIdx.x;
    const int lane = tid & 31;
    const int wid  = tid >> 5;
    const int warpRow = (wid & 3) * 32;   // 0,32,64,96
    const int warpCol = (wid >> 2) * 64;  // 0,64
    const int g  = lane >> 2;             // 0..7
    const int t4 = lane & 3;              // 0..3

    const int rowBase = blockIdx.y * GBM;
    const int colBase = blockIdx.x * GBN;

    // A loader: row = tid>>2 (0..63, two passes), 4 float4-cols
    const int aRow = tid >> 2;
    const int aC   = (tid & 3) << 2;
    // B loader: 512 float4, two passes of 256
    const int bR0 = tid >> 5;             // 0..7
    const int bC0 = (tid & 31) << 2;

    float c[2][8][4];
    #pragma unroll
    for (int mi = 0; mi < 2; mi++)
        #pragma unroll
        for (int ni = 0; ni < 8; ni++)
            #pragma unroll
            for (int r = 0; r < 4; r++) c[mi][ni][r] = 0.f;

    const int T = K / GBK;

    // ---- stage loads ----
    auto loadA = [&](int buf, int k0) {
        #pragma unroll
        for (int p = 0; p < 2; p++) {
            int r  = aRow + p * 64;
            int gr = rowBase + r;
            bool pred = gr < M;
            const float* src = A + (long)(pred ? gr : 0) * K + k0 + aC;
            cp16(&As[buf][r][aC], src, pred);
        }
    };
    auto loadB = [&](int buf, int k0) {
        #pragma unroll
        for (int p = 0; p < 2; p++) {
            int r = bR0 + p * 8;
            const float* src = Bm + (long)(k0 + r) * N + colBase + bC0;
            cp16(&Bs[buf][r][bC0], src, true);
        }
    };

    loadA(0, 0); loadB(0, 0); cp_commit();

    for (int t = 0; t < T; t++) {
        cp_wait0();
        __syncthreads();
        if (t + 1 < T) {
            loadA((t + 1) & 1, (t + 1) * GBK);
            loadB((t + 1) & 1, (t + 1) * GBK);
            cp_commit();
        }
        const int buf = t & 1;

        #pragma unroll
        for (int kk = 0; kk < 2; kk++) {
            const int k0 = kk * 8;
            uint32_t a[2][4];
            #pragma unroll
            for (int mi = 0; mi < 2; mi++) {
                int r = warpRow + mi * 16;
                a[mi][0] = __float_as_uint(As[buf][r + g    ][k0 + t4    ]);
                a[mi][1] = __float_as_uint(As[buf][r + g + 8][k0 + t4    ]);
                a[mi][2] = __float_as_uint(As[buf][r + g    ][k0 + t4 + 4]);
                a[mi][3] = __float_as_uint(As[buf][r + g + 8][k0 + t4 + 4]);
            }
            uint32_t b[8][2];
            #pragma unroll
            for (int ni = 0; ni < 8; ni++) {
                int cc = warpCol + ni * 8 + g;
                b[ni][0] = __float_as_uint(Bs[buf][k0 + t4    ][cc]);
                b[ni][1] = __float_as_uint(Bs[buf][k0 + t4 + 4][cc]);
            }
            #pragma unroll
            for (int mi = 0; mi < 2; mi++)
                #pragma unroll
                for (int ni = 0; ni < 8; ni++)
                    mma_tf32(c[mi][ni], a[mi], b[ni]);
        }
        __syncthreads();
    }

    // ---- epilogue ----
    #pragma unroll
    for (int ni = 0; ni < 8; ni++) {
        int col = colBase + warpCol + ni * 8 + t4 * 2;
        float b0 = 0.f, b1 = 0.f;
        if (bias) { b0 = bias[col]; b1 = bias[col + 1]; }
        #pragma unroll
        for (int mi = 0; mi < 2; mi++) {
            int row0 = rowBase + warpRow + mi * 16 + g;
            int row1 = row0 + 8;
            if (row0 < M) {
                float2 o; o.x = c[mi][ni][0] + b0; o.y = c[mi][ni][1] + b1;
                *reinterpret_cast<float2*>(&C[(long)row0 * N + col]) = o;
            }
            if (row1 < M) {
                float2 o; o.x = c[mi][ni][2] + b0; o.y = c[mi][ni][3] + b1;
                *reinterpret_cast<float2*>(&C[(long)row1 * N + col]) = o;
            }
        }
    }
}

// ---------------- fused flash-style attention (lane-pair per query row) ----------------
// grid = (N/128, H, B), 256 threads; lane pair (2k,2k+1) handles one row, 32 dims each.
__global__ __launch_bounds__(256) void attn_kernel(
    const float* __restrict__ q, const float* __restrict__ kbuf,
    const float* __restrict__ vbuf, float* __restrict__ out)
{
    __shared__ float Ks[M_][D_];
    __shared__ float Vs[M_][D_];

    const int b = blockIdx.z, h = blockIdx.y;
    const int tid = threadIdx.x;
    const int rowIb = tid >> 1;
    const int half  = tid & 1;
    const int n = blockIdx.x * 128 + rowIb;
    const int dbase = half * 32;
    const float scale = 0.125f;  // 1/sqrt(64)

    const long kvbase = ((long)b * M_) * INNER + h * D_;
    for (int idx = tid; idx < M_ * (D_ / 4); idx += 256) {
        int m  = idx >> 4;
        int d4 = (idx & 15) << 2;
        *reinterpret_cast<float4*>(&Ks[m][d4]) =
            *reinterpret_cast<const float4*>(&kbuf[kvbase + (long)m * INNER + d4]);
        *reinterpret_cast<float4*>(&Vs[m][d4]) =
            *reinterpret_cast<const float4*>(&vbuf[kvbase + (long)m * INNER + d4]);
    }
    __syncthreads();

    float qr[32];
    const long qbase = ((long)b * N_ + n) * INNER + h * D_;
    #pragma unroll
    for (int d4 = 0; d4 < 32; d4 += 4) {
        float4 t = *reinterpret_cast<const float4*>(&q[qbase + dbase + d4]);
        qr[d4 + 0] = t.x * scale; qr[d4 + 1] = t.y * scale;
        qr[d4 + 2] = t.z * scale; qr[d4 + 3] = t.w * scale;
    }

    float acc[32];
    #pragma unroll
    for (int d = 0; d < 32; d++) acc[d] = 0.f;
    float mrun = -1e30f, srun = 0.f;

    for (int m = 0; m < M_; m++) {
        float sp = 0.f;
        #pragma unroll
        for (int d = 0; d < 32; d++) sp += qr[d] * Ks[m][dbase + d];
        float s = sp + __shfl_xor_sync(0xffffffffu, sp, 1);
        if (s <= mrun) {
            float p = __expf(s - mrun);
            srun += p;
            #pragma unroll
            for (int d = 0; d < 32; d++) acc[d] += p * Vs[m][dbase + d];
        } else {
            float corr = __expf(mrun - s);
            mrun = s;
            srun = srun * corr + 1.f;
            #pragma unroll
            for (int d = 0; d < 32; d++) acc[d] = acc[d] * corr + Vs[m][dbase + d];
        }
    }

    const float inv = 1.f / srun;
    #pragma unroll
    for (int d4 = 0; d4 < 32; d4 += 4) {
        float4 o;
        o.x = tf32r(acc[d4 + 0] * inv); o.y = tf32r(acc[d4 + 1] * inv);
        o.z = tf32r(acc[d4 + 2] * inv); o.w = tf32r(acc[d4 + 3] * inv);
        *reinterpret_cast<float4*>(&out[qbase + dbase + d4]) = o;
    }
}

// ---------------- launch ----------------
extern "C" void kernel_launch(void* const* d_in, const int* in_sizes, int n_in,
                              void* d_out, int out_size)
{
    const float* x   = (const float*)d_in[0];
    const float* ctx = (const float*)d_in[1];
    const float* Wq  = (const float*)d_in[2];
    const float* Wk  = (const float*)d_in[3];
    const float* Wv  = (const float*)d_in[4];
    const float* Wo  = (const float*)d_in[5];
    const float* bo  = (const float*)d_in[6];
    float* out = (float*)d_out;

    float *xr, *cr, *wq, *wk, *wv, *wo, *qb, *kb, *vb, *ab;
    cudaGetSymbolAddress((void**)&xr, g_xr);
    cudaGetSymbolAddress((void**)&cr, g_cr);
    cudaGetSymbolAddress((void**)&wq, g_wq);
    cudaGetSymbolAddress((void**)&wk, g_wk);
    cudaGetSymbolAddress((void**)&wv, g_wv);
    cudaGetSymbolAddress((void**)&wo, g_wo);
    cudaGetSymbolAddress((void**)&qb, g_q);
    cudaGetSymbolAddress((void**)&kb, g_k);
    cudaGetSymbolAddress((void**)&vb, g_v);
    cudaGetSymbolAddress((void**)&ab, g_a);

    auto roundit = [](const float* src, float* dst, long n) {
        int n4 = (int)(n / 4);
        tf32_round<<<(n4 + 255) / 256, 256>>>((const float4*)src, (float4*)dst, n4);
    };

    // Pre-round all GEMM operands to tf32 (RNA) so GEMMs can feed mma raw.
    roundit(x,   xr, (long)B_ * N_ * QDIM);
    roundit(ctx, cr, (long)B_ * M_ * CDIM);
    roundit(Wq,  wq, (long)QDIM * INNER);
    roundit(Wk,  wk, (long)CDIM * INNER);
    roundit(Wv,  wv, (long)CDIM * INNER);
    roundit(Wo,  wo, (long)INNER * QDIM);

    // k = ctx @ Wk, v = ctx @ Wv   (1232 x 512, K=768) — ragged M, guarded
    sgemm_tf32<<<dim3(INNER / GBN, (B_ * M_ + GBM - 1) / GBM), 256>>>(
        B_ * M_, INNER, CDIM, cr, wk, nullptr, kb);
    sgemm_tf32<<<dim3(INNER / GBN, (B_ * M_ + GBM - 1) / GBM), 256>>>(
        B_ * M_, INNER, CDIM, cr, wv, nullptr, vb);

    // q = x @ Wq   (65536 x 512, K=1024)
    sgemm_tf32<<<dim3(INNER / GBN, (B_ * N_) / GBM), 256>>>(
        B_ * N_, INNER, QDIM, xr, wq, nullptr, qb);

    // attention (emits tf32-rounded activations)
    attn_kernel<<<dim3(N_ / 128, H_, B_), 256>>>(qb, kb, vb, ab);

    // out = attn @ Wo + bo   (65536 x 1024, K=512)
    sgemm_tf32<<<dim3(QDIM / GBN, (B_ * N_) / GBM), 256>>>(
        B_ * N_, QDIM, INNER, ab, wo, bo, out);
}